// round 15
// baseline (speedup 1.0000x reference)
#include <cuda_runtime.h>
#include <cuda_bf16.h>
#include <math.h>
#include <stdint.h>

// ---------------- problem constants ----------------
#define DIM      192
#define HEADS    6
#define HD       32
#define HIDDEN   768
#define NLON     15
#define NW       64
#define NTOK     144
#define WTOK     138240
#define LTOK     131040
#define EPSLN    1e-5f
#define QKSCALE  0.17677669529663687f

// ---------------- device scratch ----------------
__device__ __nv_bfloat16 g_h   [(size_t)WTOK * DIM];
__device__ __nv_bfloat16 g_qkv [(size_t)WTOK * 3 * DIM];
__device__ __nv_bfloat16 g_att [(size_t)WTOK * DIM];
__device__ float         g_x1  [(size_t)LTOK * DIM];
__device__ __nv_bfloat16 g_h2  [(size_t)LTOK * DIM];
__device__ __nv_bfloat16 g_fc1 [(size_t)LTOK * HIDDEN];
__device__ __nv_bfloat16 g_wq  [576 * 192];
__device__ __nv_bfloat16 g_wp  [192 * 192];
__device__ __nv_bfloat16 g_w1  [768 * 192];
__device__ __nv_bfloat16 g_w2  [192 * 768];
__device__ __nv_bfloat16 g_bmask[(size_t)2 * NW * HEADS * NTOK * NTOK];  // 31.8 MB

// ---------------- prep kernels ----------------
__global__ void cvtall_kernel(const float* __restrict__ qkvw,
                              const float* __restrict__ projw,
                              const float* __restrict__ fc1w,
                              const float* __restrict__ fc2w) {
    int i = blockIdx.x * 256 + threadIdx.x;
    if (i < 110592)       g_wq[i]          = __float2bfloat16(qkvw[i]);
    else if (i < 147456)  g_wp[i - 110592] = __float2bfloat16(projw[i - 110592]);
    else if (i < 294912)  g_w1[i - 147456] = __float2bfloat16(fc1w[i - 147456]);
    else if (i < 442368)  g_w2[i - 294912] = __float2bfloat16(fc2w[i - 294912]);
}

// combined (bias + shift-mask) matrices: [cls][iw][head][144][144] bf16
__global__ void bmask_kernel(const float* __restrict__ bt) {
    __shared__ float tb[3312];
    __shared__ int rb[144], cm[144], rg[144];
    int b = blockIdx.x;
    int cls = b / 384, rem = b % 384;
    int iw = rem / 6;
    int ipl = iw >> 4, ilat = iw & 15;
    int tid = threadIdx.x;
    for (int i = tid; i < 3312; i += 256) tb[i] = bt[(size_t)i * 384 + rem];
    for (int i = tid; i < 144; i += 256) {
        int z = i / 72, h = (i / 12) % 6, w = i % 12;
        cm[i] = 1656 * z + 138 * h - w;
        rb[i] = 828 * z + 23 * h + w + 11;
        int pl = ipl * 2 + z, lat = ilat * 6 + h;
        int lonr = cls ? (w < 6 ? 0 : 1) : 0;
        rg[i] = (pl < 6 ? 0 : (pl < 7 ? 1 : 2)) * 9
              + (lat < 90 ? 0 : (lat < 93 ? 1 : 2)) * 3 + lonr;
    }
    __syncthreads();
    __nv_bfloat16* dst = g_bmask + (size_t)b * (NTOK * NTOK);
    for (int e = tid; e < NTOK * NTOK; e += 256) {
        int r = e / 144, c = e - r * 144;
        float v = tb[rb[r] + cm[c]];
        if (rg[r] != rg[c]) v -= 100.f;
        dst[e] = __float2bfloat16(v);
    }
}

// ---------------- kernel 1: LN1 + pad + roll + window partition ----------------
__global__ void ln1_window_kernel(const float* __restrict__ x,
                                  const float* __restrict__ w1,
                                  const float* __restrict__ b1) {
    int warp = threadIdx.x >> 5, lane = threadIdx.x & 31;
    int t = blockIdx.x * 8 + warp;
    int ilon = t / (NW * NTOK);
    int rem  = t % (NW * NTOK);
    int iw = rem / NTOK, n = rem % NTOK;
    int ipl = iw >> 4, ilat = iw & 15;
    int z = n / 72, hh = (n / 12) % 6, ww = n % 12;
    int pl_s  = (ipl * 2 + z + 1) & 7;
    int lat_p = ilat * 6 + hh + 3; if (lat_p >= 96) lat_p -= 96;
    int lat_s = lat_p - 2;
    int lon_s = ilon * 12 + ww + 6; if (lon_s >= 180) lon_s -= 180;

    __nv_bfloat16* dst = g_h + (size_t)t * DIM;
    if (lat_s >= 0 && lat_s < 91) {
        const float* src = x + ((size_t)(pl_s * 91 + lat_s) * 180 + lon_s) * DIM;
        float v[6]; float s = 0.f, qq = 0.f;
        #pragma unroll
        for (int j = 0; j < 6; j++) {
            v[j] = src[lane + 32 * j];
            s += v[j]; qq += v[j] * v[j];
        }
        #pragma unroll
        for (int o = 16; o > 0; o >>= 1) {
            s  += __shfl_xor_sync(0xffffffffu, s, o);
            qq += __shfl_xor_sync(0xffffffffu, qq, o);
        }
        float mean = s * (1.f / 192.f);
        float var  = qq * (1.f / 192.f) - mean * mean;
        float rs = rsqrtf(var + EPSLN);
        #pragma unroll
        for (int j = 0; j < 6; j++) {
            int c = lane + 32 * j;
            dst[c] = __float2bfloat16((v[j] - mean) * rs * w1[c] + b1[c]);
        }
    } else {
        #pragma unroll
        for (int j = 0; j < 6; j++) dst[lane + 32 * j] = __float2bfloat16(0.f);
    }
}

// ---------------- shared MMA helpers ----------------
__device__ __forceinline__ void ldsm4(uint32_t r[4], uint32_t addr) {
    asm volatile("ldmatrix.sync.aligned.m8n8.x4.shared.b16 {%0,%1,%2,%3}, [%4];"
                 : "=r"(r[0]), "=r"(r[1]), "=r"(r[2]), "=r"(r[3]) : "r"(addr));
}
__device__ __forceinline__ void ldsm4t(uint32_t r[4], uint32_t addr) {
    asm volatile("ldmatrix.sync.aligned.m8n8.x4.trans.shared.b16 {%0,%1,%2,%3}, [%4];"
                 : "=r"(r[0]), "=r"(r[1]), "=r"(r[2]), "=r"(r[3]) : "r"(addr));
}
__device__ __forceinline__ void mma_bf16(float c[4], const uint32_t a[4],
                                         uint32_t b0, uint32_t b1) {
    asm volatile(
        "mma.sync.aligned.m16n8k16.row.col.f32.bf16.bf16.f32 "
        "{%0,%1,%2,%3}, {%4,%5,%6,%7}, {%8,%9}, {%0,%1,%2,%3};"
        : "+f"(c[0]), "+f"(c[1]), "+f"(c[2]), "+f"(c[3])
        : "r"(a[0]), "r"(a[1]), "r"(a[2]), "r"(a[3]), "r"(b0), "r"(b1));
}
__device__ __forceinline__ uint32_t pack_bf2(float a, float b) {
    __nv_bfloat162 t = __floats2bfloat162_rn(a, b);
    uint32_t u;
    memcpy(&u, &t, 4);
    return u;
}
__device__ __forceinline__ uint32_t swz(int row, int kb) {
    int line  = row >> 1;
    int chunk = ((row & 1) << 2) | (kb >> 4);
    int phys  = chunk ^ (line & 7);
    return (uint32_t)(line * 128 + phys * 16 + (kb & 15));
}
__device__ __forceinline__ void cpasync16(uint32_t dst, const void* src, int sz) {
    asm volatile("cp.async.cg.shared.global [%0], [%1], 16, %2;"
                 :: "r"(dst), "l"(src), "r"(sz));
}

// ---------------- main bf16 GEMM (templated K, MODE) — R14 proven shape ----------------
// tile 256x64, BK=32, 4-stage cp.async ring, one __syncthreads per stage
#define ASTAGE 16384
#define BSTAGE 4096
#define STAGE  (ASTAGE + BSTAGE)
#define NSTG   4

template <int K, int MODE>
__global__ __launch_bounds__(256, 2) void gemm_tpl_kernel(
        const __nv_bfloat16* __restrict__ A,
        const __nv_bfloat16* __restrict__ W,
        const float* __restrict__ bias,
        const float* __restrict__ res,
        __nv_bfloat16* __restrict__ Cb,
        float* __restrict__ Cf,
        int M, int N) {
    extern __shared__ __align__(128) uint8_t smem[];
    const uint32_t sbase = (uint32_t)__cvta_generic_to_shared(smem);
    constexpr int NSTAGE = K / 32;
    static_assert(NSTAGE >= 4, "need at least 4 k-stages");

    const int tid = threadIdx.x, warp = tid >> 5, lane = tid & 31;
    const int wm = warp & 3, wn = warp >> 2;
    const int g = lane >> 2, tig = lane & 3;
    const int row0 = blockIdx.y * 256;
    const int col0 = blockIdx.x * 64;

    float acc[4][4][4] = {};

    const int quad = lane >> 3;
    const int rr = (quad & 1) * 8 + (lane & 7);
    const int kbq = (quad >> 1) * 16;
    const int ar = lane & 15, ac = (lane >> 4) * 16;
    const int lm = tid >> 2, lc = tid & 3;

    uint32_t aOf[4], bOf;
    const __nv_bfloat16* aP[4];
    int aSz[4];
    #pragma unroll
    for (int j = 0; j < 4; j++) {
        int m = lm + j * 64;
        aOf[j] = swz(m, lc * 16);
        aP[j]  = A + (size_t)(row0 + m) * K + lc * 8;
        aSz[j] = (row0 + m < M) ? 16 : 0;
    }
    bOf = swz(lm, lc * 16);
    const __nv_bfloat16* bP = W + (size_t)(col0 + lm) * K + lc * 8;

    auto load = [&](int stage) {
        uint32_t aB = sbase + (uint32_t)(stage & 3) * STAGE;
        #pragma unroll
        for (int j = 0; j < 4; j++) {
            cpasync16(aB + aOf[j], aP[j], aSz[j]);
            aP[j] += 32;
        }
        cpasync16(aB + ASTAGE + bOf, bP, 16);
        bP += 32;
        asm volatile("cp.async.commit_group;");
    };

    load(0); load(1); load(2);

    #pragma unroll
    for (int s = 0; s < NSTAGE; s++) {
        if (NSTAGE - 1 - s >= 2)      asm volatile("cp.async.wait_group 2;");
        else if (NSTAGE - 1 - s == 1) asm volatile("cp.async.wait_group 1;");
        else                          asm volatile("cp.async.wait_group 0;");
        __syncthreads();

        uint32_t aB = sbase + (uint32_t)(s & 3) * STAGE;
        uint32_t bB = aB + ASTAGE;
        #pragma unroll
        for (int ks = 0; ks < 2; ks++) {
            uint32_t afr[4][4], bfr[4][2];
            #pragma unroll
            for (int mi = 0; mi < 4; mi++)
                ldsm4(afr[mi], aB + swz(wm * 64 + mi * 16 + ar, ks * 32 + ac));
            #pragma unroll
            for (int np = 0; np < 2; np++) {
                uint32_t r4[4];
                ldsm4(r4, bB + swz(wn * 32 + np * 16 + rr, ks * 32 + kbq));
                bfr[np * 2 + 0][0] = r4[0]; bfr[np * 2 + 0][1] = r4[2];
                bfr[np * 2 + 1][0] = r4[1]; bfr[np * 2 + 1][1] = r4[3];
            }
            #pragma unroll
            for (int mi = 0; mi < 4; mi++)
                #pragma unroll
                for (int ni = 0; ni < 4; ni++)
                    mma_bf16(acc[mi][ni], afr[mi], bfr[ni][0], bfr[ni][1]);
        }

        if (s + 3 < NSTAGE) load(s + 3);
    }

    #pragma unroll
    for (int mi = 0; mi < 4; mi++) {
        #pragma unroll
        for (int hi = 0; hi < 2; hi++) {
            int r = row0 + wm * 64 + mi * 16 + g + hi * 8;
            if (r >= M) continue;
            #pragma unroll
            for (int ni = 0; ni < 4; ni++) {
                int c = col0 + wn * 32 + ni * 8 + 2 * tig;
                float v0 = acc[mi][ni][hi * 2 + 0] + bias[c];
                float v1 = acc[mi][ni][hi * 2 + 1] + bias[c + 1];
                if constexpr (MODE == 1) {
                    v0 = 0.5f * v0 * (1.0f + erff(v0 * 0.70710678118654752440f));
                    v1 = 0.5f * v1 * (1.0f + erff(v1 * 0.70710678118654752440f));
                }
                if constexpr (MODE == 2) {
                    const float2 rv = *(const float2*)(res + (size_t)r * N + c);
                    *(float2*)(Cf + (size_t)r * N + c) = make_float2(v0 + rv.x, v1 + rv.y);
                } else {
                    *(__nv_bfloat162*)(Cb + (size_t)r * N + c) = __floats2bfloat162_rn(v0, v1);
                }
            }
        }
    }
}

// ---------------- proj GEMM + fused scatter/residual/LN2 (verified in R7) ----------------
// BM=128, BN=192, BK=32, 2-stage double buffer, 8 warps (4m x 2n), warp 32x96
#define P_ASTAGE 8192
#define P_BSTAGE 12288
#define P_STAGE  (P_ASTAGE + P_BSTAGE)

#define P_LOAD_STAGE(aB, bB, kofs)                                                 \
    {                                                                              \
        int arow = tid >> 1;                                                       \
        _Pragma("unroll")                                                          \
        for (int j = 0; j < 2; j++) {                                              \
            int chunk = (tid & 1) * 2 + j;                                         \
            const void* srcp = A + (size_t)(row0 + arow) * 192 + (kofs) + chunk * 8; \
            cpasync16((aB) + swz(arow, chunk * 16), srcp, 16);                     \
        }                                                                          \
        _Pragma("unroll")                                                          \
        for (int j = 0; j < 3; j++) {                                              \
            int idx = tid + 256 * j;                                               \
            int brow = idx >> 2, chunk = idx & 3;                                  \
            cpasync16((bB) + swz(brow, chunk * 16),                                \
                      W + (size_t)brow * 192 + (kofs) + chunk * 8, 16);            \
        }                                                                          \
        asm volatile("cp.async.commit_group;");                                    \
    }

__global__ __launch_bounds__(256) void proj_ln_kernel(
        const __nv_bfloat16* __restrict__ A,
        const __nv_bfloat16* __restrict__ W,
        const float* __restrict__ bias,
        const float* __restrict__ x,
        const float* __restrict__ w2,
        const float* __restrict__ b2) {
    __shared__ __align__(128) uint8_t smem[2 * P_STAGE];
    __shared__ float redS[128][2], redQ[128][2];
    uint32_t sbase = (uint32_t)__cvta_generic_to_shared(smem);

    const int tid = threadIdx.x, warp = tid >> 5, lane = tid & 31;
    const int wm = warp & 3, wn = warp >> 2;
    const int g = lane >> 2, tig = lane & 3;
    const int row0 = blockIdx.x * 128;

    float acc[2][12][4] = {};
    const int quad = lane >> 3;
    const int rr = (quad & 1) * 8 + (lane & 7);
    const int kbq = (quad >> 1) * 16;
    const int ar = lane & 15, ac = (lane >> 4) * 16;

    P_LOAD_STAGE(sbase, sbase + P_ASTAGE, 0);

    #pragma unroll
    for (int s = 0; s < 6; s++) {
        if (s + 1 < 6) {
            uint32_t aB = sbase + ((s + 1) & 1) * P_STAGE;
            P_LOAD_STAGE(aB, aB + P_ASTAGE, (s + 1) * 32);
            asm volatile("cp.async.wait_group 1;");
        } else {
            asm volatile("cp.async.wait_group 0;");
        }
        __syncthreads();
        uint32_t aB = sbase + (s & 1) * P_STAGE, bB = aB + P_ASTAGE;
        #pragma unroll
        for (int ks = 0; ks < 2; ks++) {
            uint32_t afr[2][4], bfr[12][2];
            #pragma unroll
            for (int mi = 0; mi < 2; mi++)
                ldsm4(afr[mi], aB + swz(wm * 32 + mi * 16 + ar, ks * 32 + ac));
            #pragma unroll
            for (int np = 0; np < 6; np++) {
                uint32_t r4[4];
                ldsm4(r4, bB + swz(wn * 96 + np * 16 + rr, ks * 32 + kbq));
                bfr[np * 2 + 0][0] = r4[0]; bfr[np * 2 + 0][1] = r4[2];
                bfr[np * 2 + 1][0] = r4[1]; bfr[np * 2 + 1][1] = r4[3];
            }
            #pragma unroll
            for (int mi = 0; mi < 2; mi++)
                #pragma unroll
                for (int ni = 0; ni < 12; ni++)
                    mma_bf16(acc[mi][ni], afr[mi], bfr[ni][0], bfr[ni][1]);
        }
        __syncthreads();
    }

    // fused epilogue phase 1: residual add + row stats
    int toks[2][2]; bool vals[2][2];
    #pragma unroll
    for (int mi = 0; mi < 2; mi++) {
        #pragma unroll
        for (int hi = 0; hi < 2; hi++) {
            int rl = wm * 32 + mi * 16 + g + hi * 8;
            int t = row0 + rl;
            int ilon = t / (NW * NTOK);
            int rem  = t % (NW * NTOK);
            int iw = rem / NTOK, n = rem % NTOK;
            int ipl = iw >> 4, ilat = iw & 15;
            int z = n / 72, hh = (n / 12) % 6, ww = n % 12;
            int pl_s  = (ipl * 2 + z + 1) & 7;
            int lat_p = ilat * 6 + hh + 3; if (lat_p >= 96) lat_p -= 96;
            int lat_s = lat_p - 2;
            int lon_s = ilon * 12 + ww + 6; if (lon_s >= 180) lon_s -= 180;
            bool valid = (lat_s >= 0 && lat_s < 91);
            int tok = (pl_s * 91 + lat_s) * 180 + lon_s;
            vals[mi][hi] = valid; toks[mi][hi] = tok;

            float s = 0.f, q = 0.f;
            if (valid) {
                const float* xr = x + (size_t)tok * DIM;
                #pragma unroll
                for (int ni = 0; ni < 12; ni++) {
                    int c = wn * 96 + ni * 8 + 2 * tig;
                    float2 xv = *(const float2*)(xr + c);
                    float v0 = acc[mi][ni][hi * 2 + 0] + bias[c]     + xv.x;
                    float v1 = acc[mi][ni][hi * 2 + 1] + bias[c + 1] + xv.y;
                    acc[mi][ni][hi * 2 + 0] = v0;
                    acc[mi][ni][hi * 2 + 1] = v1;
                    s += v0 + v1; q += v0 * v0 + v1 * v1;
                }
            }
            s += __shfl_xor_sync(0xffffffffu, s, 1);
            s += __shfl_xor_sync(0xffffffffu, s, 2);
            q += __shfl_xor_sync(0xffffffffu, q, 1);
            q += __shfl_xor_sync(0xffffffffu, q, 2);
            if (tig == 0) { redS[rl][wn] = s; redQ[rl][wn] = q; }
        }
    }
    __syncthreads();

    // phase 2: normalize + write
    #pragma unroll
    for (int mi = 0; mi < 2; mi++) {
        #pragma unroll
        for (int hi = 0; hi < 2; hi++) {
            if (!vals[mi][hi]) continue;
            int rl = wm * 32 + mi * 16 + g + hi * 8;
            int tok = toks[mi][hi];
            float s = redS[rl][0] + redS[rl][1];
            float q = redQ[rl][0] + redQ[rl][1];
            float mean = s * (1.f / 192.f);
            float var  = q * (1.f / 192.f) - mean * mean;
            float rs = rsqrtf(var + EPSLN);
            float* x1r = g_x1 + (size_t)tok * DIM;
            __nv_bfloat16* h2r = g_h2 + (size_t)tok * DIM;
            #pragma unroll
            for (int ni = 0; ni < 12; ni++) {
                int c = wn * 96 + ni * 8 + 2 * tig;
                float v0 = acc[mi][ni][hi * 2 + 0];
                float v1 = acc[mi][ni][hi * 2 + 1];
                *(float2*)(x1r + c) = make_float2(v0, v1);
                float n0 = (v0 - mean) * rs * w2[c]     + b2[c];
                float n1 = (v1 - mean) * rs * w2[c + 1] + b2[c + 1];
                *(__nv_bfloat162*)(h2r + c) = __floats2bfloat162_rn(n0, n1);
            }
        }
    }
}

// ---------------- kernel 3: tensor-core windowed attention ----------------
__device__ __forceinline__ uint32_t swa(uint32_t base, int row, int chunk) {
    return base + row * 64 + ((chunk ^ ((row >> 1) & 3)) << 4);
}

__global__ __launch_bounds__(288, 2) void attn_kernel() {
    __shared__ __align__(128) __nv_bfloat16 sQ[144 * 32];
    __shared__ __align__(128) __nv_bfloat16 sK[144 * 32];
    __shared__ __align__(128) __nv_bfloat16 sV[144 * 32];

    const int blk = blockIdx.x;
    const int gwin = blk / HEADS, head = blk % HEADS;
    const int ilon = gwin / NW, iw = gwin % NW;
    const int tid = threadIdx.x;
    const size_t base = (size_t)gwin * NTOK;

    {
        const __nv_bfloat16* tb = g_qkv + base * 576 + head * 32;
        for (int i = tid; i < 576; i += 288) {
            int n = i >> 2, c = i & 3;
            int off = n * 32 + ((c ^ ((n >> 1) & 3)) << 3);
            const __nv_bfloat16* tp = tb + (size_t)n * 576 + c * 8;
            *(uint4*)(sQ + off) = *(const uint4*)(tp);
            *(uint4*)(sK + off) = *(const uint4*)(tp + 192);
            *(uint4*)(sV + off) = *(const uint4*)(tp + 384);
        }
    }
    __syncthreads();

    const uint32_t qB = (uint32_t)__cvta_generic_to_shared(sQ);
    const uint32_t kB = (uint32_t)__cvta_generic_to_shared(sK);
    const uint32_t vB = (uint32_t)__cvta_generic_to_shared(sV);

    const int warp = tid >> 5, lane = tid & 31;
    const int g = lane >> 2, tig = lane & 3;
    const int m0 = warp * 16;

    uint32_t aq[2][4];
    #pragma unroll
    for (int kq = 0; kq < 2; kq++)
        ldsm4(aq[kq], swa(qB, m0 + (lane & 15), kq * 2 + (lane >> 4)));

    const __nv_bfloat16* bm = g_bmask
        + ((size_t)((ilon == 14 ? 1 : 0) * 384 + iw * HEADS + head)) * (NTOK * NTOK);
    const int r0 = m0 + g, r1 = r0 + 8;

    float den0 = 0.f, den1 = 0.f;
    float o[4][4] = {};

    #pragma unroll
    for (int ph = 0; ph < 2; ph++) {
        const int ntS = ph ? 10 : 0, ntE = ph ? 18 : 10;
        const int kcS = ph ? 5 : 0,  kcE = ph ? 9 : 5;

        float acc[10][4];
        #pragma unroll
        for (int j = 0; j < 10; j++)
            #pragma unroll
            for (int q = 0; q < 4; q++) acc[j][q] = 0.f;

        for (int nt = ntS; nt < ntE; nt++) {
            uint32_t bk[4];
            ldsm4(bk, swa(kB, nt * 8 + (lane & 7), lane >> 3));
            mma_bf16(acc[nt - ntS], aq[0], bk[0], bk[1]);
            mma_bf16(acc[nt - ntS], aq[1], bk[2], bk[3]);
        }

        uint32_t paLo[10], paHi[10];
        for (int nt = ntS; nt < ntE; nt++) {
            int j = nt - ntS;
            int c0 = nt * 8 + 2 * tig;
            __nv_bfloat162 b0 = *(const __nv_bfloat162*)(bm + (size_t)r0 * 144 + c0);
            __nv_bfloat162 b1 = *(const __nv_bfloat162*)(bm + (size_t)r1 * 144 + c0);
            float p0 = __expf(fmaf(acc[j][0], QKSCALE, __bfloat162float(b0.x)));
            float p1 = __expf(fmaf(acc[j][1], QKSCALE, __bfloat162float(b0.y)));
            float p2 = __expf(fmaf(acc[j][2], QKSCALE, __bfloat162float(b1.x)));
            float p3 = __expf(fmaf(acc[j][3], QKSCALE, __bfloat162float(b1.y)));
            den0 += p0 + p1; den1 += p2 + p3;
            paLo[j] = pack_bf2(p0, p1);
            paHi[j] = pack_bf2(p2, p3);
        }

        for (int kc = kcS; kc < kcE; kc++) {
            int j2 = 2 * (kc - kcS);
            uint32_t Afr[4] = {paLo[j2], paHi[j2], paLo[j2 + 1], paHi[j2 + 1]};
            #pragma unroll
            for (int np = 0; np < 2; np++) {
                uint32_t bv[4];
                ldsm4t(bv, swa(vB, kc * 16 + ((lane >> 3) & 1) * 8 + (lane & 7),
                               np * 2 + (lane >> 4)));
                mma_bf16(o[np * 2 + 0], Afr, bv[0], bv[1]);
                mma_bf16(o[np * 2 + 1], Afr, bv[2], bv[3]);
            }
        }
    }

    den0 += __shfl_xor_sync(0xffffffffu, den0, 1);
    den0 += __shfl_xor_sync(0xffffffffu, den0, 2);
    den1 += __shfl_xor_sync(0xffffffffu, den1, 1);
    den1 += __shfl_xor_sync(0xffffffffu, den1, 2);
    float inv0 = 1.f / den0, inv1 = 1.f / den1;

    __nv_bfloat16* ob = g_att + base * DIM + head * HD;
    #pragma unroll
    for (int nt4 = 0; nt4 < 4; nt4++) {
        int col = nt4 * 8 + 2 * tig;
        *(__nv_bfloat162*)(ob + (size_t)r0 * DIM + col) =
            __floats2bfloat162_rn(o[nt4][0] * inv0, o[nt4][1] * inv0);
        *(__nv_bfloat162*)(ob + (size_t)r1 * DIM + col) =
            __floats2bfloat162_rn(o[nt4][2] * inv1, o[nt4][3] * inv1);
    }
}

// ---------------- launcher ----------------
extern "C" void kernel_launch(void* const* d_in, const int* in_sizes, int n_in,
                              void* d_out, int out_size) {
    const float* x     = (const float*)d_in[0];
    const float* n1w   = (const float*)d_in[1];
    const float* n1b   = (const float*)d_in[2];
    const float* qkvw  = (const float*)d_in[3];
    const float* qkvb  = (const float*)d_in[4];
    const float* btab  = (const float*)d_in[5];
    const float* projw = (const float*)d_in[6];
    const float* projb = (const float*)d_in[7];
    const float* n2w   = (const float*)d_in[8];
    const float* n2b   = (const float*)d_in[9];
    const float* fc1w  = (const float*)d_in[10];
    const float* fc1b  = (const float*)d_in[11];
    const float* fc2w  = (const float*)d_in[12];
    const float* fc2b  = (const float*)d_in[13];
    float* out = (float*)d_out;

    __nv_bfloat16 *p_h, *p_qkv, *p_att, *p_h2, *p_fc1;
    __nv_bfloat16 *p_wq, *p_wp, *p_w1, *p_w2;
    float *p_x1;
    cudaGetSymbolAddress((void**)&p_h,    g_h);
    cudaGetSymbolAddress((void**)&p_qkv,  g_qkv);
    cudaGetSymbolAddress((void**)&p_att,  g_att);
    cudaGetSymbolAddress((void**)&p_x1,   g_x1);
    cudaGetSymbolAddress((void**)&p_h2,   g_h2);
    cudaGetSymbolAddress((void**)&p_fc1,  g_fc1);
    cudaGetSymbolAddress((void**)&p_wq,   g_wq);
    cudaGetSymbolAddress((void**)&p_wp,   g_wp);
    cudaGetSymbolAddress((void**)&p_w1,   g_w1);
    cudaGetSymbolAddress((void**)&p_w2,   g_w2);

    static int s_init = 0;
    static cudaStream_t sW, sB;
    static cudaEvent_t evFork, evW, evB;
    if (!s_init) {
        cudaFuncSetAttribute(gemm_tpl_kernel<192, 0>,
                             cudaFuncAttributeMaxDynamicSharedMemorySize, NSTG * STAGE);
        cudaFuncSetAttribute(gemm_tpl_kernel<192, 1>,
                             cudaFuncAttributeMaxDynamicSharedMemorySize, NSTG * STAGE);
        cudaFuncSetAttribute(gemm_tpl_kernel<768, 2>,
                             cudaFuncAttributeMaxDynamicSharedMemorySize, NSTG * STAGE);
        cudaStreamCreateWithFlags(&sW, cudaStreamNonBlocking);
        cudaStreamCreateWithFlags(&sB, cudaStreamNonBlocking);
        cudaEventCreateWithFlags(&evFork, cudaEventDisableTiming);
        cudaEventCreateWithFlags(&evW,    cudaEventDisableTiming);
        cudaEventCreateWithFlags(&evB,    cudaEventDisableTiming);
        s_init = 1;
    }

    // fork side streams for prep (standard fork-join capture pattern)
    cudaEventRecord(evFork, 0);
    cudaStreamWaitEvent(sW, evFork, 0);
    cudaStreamWaitEvent(sB, evFork, 0);

    cvtall_kernel<<<(442368 + 255) / 256, 256, 0, sW>>>(qkvw, projw, fc1w, fc2w);
    cudaEventRecord(evW, sW);

    bmask_kernel<<<768, 256, 0, sB>>>(btab);
    cudaEventRecord(evB, sB);

    // main: LN1 + window partition (overlaps both prep streams)
    ln1_window_kernel<<<WTOK / 8, 256>>>(x, n1w, n1b);

    // 2. QKV gemm (needs weights)
    cudaStreamWaitEvent(0, evW, 0);
    gemm_tpl_kernel<192, 0><<<dim3(9, WTOK / 256), 256, NSTG * STAGE>>>(
        p_h, p_wq, qkvb, nullptr, p_qkv, nullptr, WTOK, 576);

    // 3. attention (needs bmask)
    cudaStreamWaitEvent(0, evB, 0);
    attn_kernel<<<NLON * NW * HEADS, 288>>>();

    // 4+5. proj gemm + scatter + residual + LN2 (fused)
    proj_ln_kernel<<<WTOK / 128, 256>>>(p_att, p_wp, projb, x, n2w, n2b);

    // 6. fc1 gemm + gelu
    gemm_tpl_kernel<192, 1><<<dim3(12, (LTOK + 255) / 256), 256, NSTG * STAGE>>>(
        p_h2, p_w1, fc1b, nullptr, p_fc1, nullptr, LTOK, 768);

    // 7. fc2 gemm + residual -> out
    gemm_tpl_kernel<768, 2><<<dim3(3, (LTOK + 255) / 256), 256, NSTG * STAGE>>>(
        p_fc1, p_w2, fc2b, p_x1, nullptr, out, LTOK, 192);
}

// round 16
// speedup vs baseline: 1.0270x; 1.0270x over previous
#include <cuda_runtime.h>
#include <cuda_bf16.h>
#include <math.h>
#include <stdint.h>

// ---------------- problem constants ----------------
#define DIM      192
#define HEADS    6
#define HD       32
#define HIDDEN   768
#define NLON     15
#define NW       64
#define NTOK     144
#define WTOK     138240
#define LTOK     131040
#define EPSLN    1e-5f
#define QKSCALE  0.17677669529663687f

// ---------------- device scratch ----------------
__device__ __nv_bfloat16 g_h   [(size_t)WTOK * DIM];
__device__ __nv_bfloat16 g_qkv [(size_t)WTOK * 3 * DIM];
__device__ __nv_bfloat16 g_att [(size_t)WTOK * DIM];
__device__ __nv_bfloat16 g_proj[(size_t)WTOK * DIM];
__device__ float         g_x1  [(size_t)LTOK * DIM];
__device__ __nv_bfloat16 g_h2  [(size_t)LTOK * DIM];
__device__ __nv_bfloat16 g_fc1 [(size_t)LTOK * HIDDEN];
__device__ __nv_bfloat16 g_wq  [576 * 192];
__device__ __nv_bfloat16 g_wp  [192 * 192];
__device__ __nv_bfloat16 g_w1  [768 * 192];
__device__ __nv_bfloat16 g_w2  [192 * 768];
__device__ __nv_bfloat16 g_bmask[(size_t)2 * NW * HEADS * NTOK * NTOK];  // 31.8 MB

// ---------------- prep kernels ----------------
__global__ void cvtall_kernel(const float* __restrict__ qkvw,
                              const float* __restrict__ projw,
                              const float* __restrict__ fc1w,
                              const float* __restrict__ fc2w) {
    int i = blockIdx.x * 256 + threadIdx.x;
    if (i < 110592)       g_wq[i]          = __float2bfloat16(qkvw[i]);
    else if (i < 147456)  g_wp[i - 110592] = __float2bfloat16(projw[i - 110592]);
    else if (i < 294912)  g_w1[i - 147456] = __float2bfloat16(fc1w[i - 147456]);
    else if (i < 442368)  g_w2[i - 294912] = __float2bfloat16(fc2w[i - 294912]);
}

// combined (bias + shift-mask) matrices: [cls][iw][head][144][144] bf16
__global__ void bmask_kernel(const float* __restrict__ bt) {
    __shared__ float tb[3312];
    __shared__ int rb[144], cm[144], rg[144];
    int b = blockIdx.x;                 // cls*384 + iw*6 + head
    int cls = b / 384, rem = b % 384;
    int iw = rem / 6;
    int ipl = iw >> 4, ilat = iw & 15;
    int tid = threadIdx.x;
    for (int i = tid; i < 3312; i += 256) tb[i] = bt[(size_t)i * 384 + rem];
    for (int i = tid; i < 144; i += 256) {
        int z = i / 72, h = (i / 12) % 6, w = i % 12;
        cm[i] = 1656 * z + 138 * h - w;
        rb[i] = 828 * z + 23 * h + w + 11;
        int pl = ipl * 2 + z, lat = ilat * 6 + h;
        int lonr = cls ? (w < 6 ? 0 : 1) : 0;
        rg[i] = (pl < 6 ? 0 : (pl < 7 ? 1 : 2)) * 9
              + (lat < 90 ? 0 : (lat < 93 ? 1 : 2)) * 3 + lonr;
    }
    __syncthreads();
    __nv_bfloat16* dst = g_bmask + (size_t)b * (NTOK * NTOK);
    for (int e = tid; e < NTOK * NTOK; e += 256) {
        int r = e / 144, c = e - r * 144;
        float v = tb[rb[r] + cm[c]];
        if (rg[r] != rg[c]) v -= 100.f;
        dst[e] = __float2bfloat16(v);
    }
}

// ---------------- kernel 1: LN1 + pad + roll + window partition ----------------
__global__ void ln1_window_kernel(const float* __restrict__ x,
                                  const float* __restrict__ w1,
                                  const float* __restrict__ b1) {
    int warp = threadIdx.x >> 5, lane = threadIdx.x & 31;
    int t = blockIdx.x * 8 + warp;
    int ilon = t / (NW * NTOK);
    int rem  = t % (NW * NTOK);
    int iw = rem / NTOK, n = rem % NTOK;
    int ipl = iw >> 4, ilat = iw & 15;
    int z = n / 72, hh = (n / 12) % 6, ww = n % 12;
    int pl_s  = (ipl * 2 + z + 1) & 7;
    int lat_p = ilat * 6 + hh + 3; if (lat_p >= 96) lat_p -= 96;
    int lat_s = lat_p - 2;
    int lon_s = ilon * 12 + ww + 6; if (lon_s >= 180) lon_s -= 180;

    __nv_bfloat16* dst = g_h + (size_t)t * DIM;
    if (lat_s >= 0 && lat_s < 91) {
        const float* src = x + ((size_t)(pl_s * 91 + lat_s) * 180 + lon_s) * DIM;
        float v[6]; float s = 0.f, qq = 0.f;
        #pragma unroll
        for (int j = 0; j < 6; j++) {
            v[j] = src[lane + 32 * j];
            s += v[j]; qq += v[j] * v[j];
        }
        #pragma unroll
        for (int o = 16; o > 0; o >>= 1) {
            s  += __shfl_xor_sync(0xffffffffu, s, o);
            qq += __shfl_xor_sync(0xffffffffu, qq, o);
        }
        float mean = s * (1.f / 192.f);
        float var  = qq * (1.f / 192.f) - mean * mean;
        float rs = rsqrtf(var + EPSLN);
        #pragma unroll
        for (int j = 0; j < 6; j++) {
            int c = lane + 32 * j;
            dst[c] = __float2bfloat16((v[j] - mean) * rs * w1[c] + b1[c]);
        }
    } else {
        #pragma unroll
        for (int j = 0; j < 6; j++) dst[lane + 32 * j] = __float2bfloat16(0.f);
    }
}

// ---------------- shared MMA helpers ----------------
__device__ __forceinline__ void ldsm4(uint32_t r[4], uint32_t addr) {
    asm volatile("ldmatrix.sync.aligned.m8n8.x4.shared.b16 {%0,%1,%2,%3}, [%4];"
                 : "=r"(r[0]), "=r"(r[1]), "=r"(r[2]), "=r"(r[3]) : "r"(addr));
}
__device__ __forceinline__ void ldsm4t(uint32_t r[4], uint32_t addr) {
    asm volatile("ldmatrix.sync.aligned.m8n8.x4.trans.shared.b16 {%0,%1,%2,%3}, [%4];"
                 : "=r"(r[0]), "=r"(r[1]), "=r"(r[2]), "=r"(r[3]) : "r"(addr));
}
__device__ __forceinline__ void mma_bf16(float c[4], const uint32_t a[4],
                                         uint32_t b0, uint32_t b1) {
    asm volatile(
        "mma.sync.aligned.m16n8k16.row.col.f32.bf16.bf16.f32 "
        "{%0,%1,%2,%3}, {%4,%5,%6,%7}, {%8,%9}, {%0,%1,%2,%3};"
        : "+f"(c[0]), "+f"(c[1]), "+f"(c[2]), "+f"(c[3])
        : "r"(a[0]), "r"(a[1]), "r"(a[2]), "r"(a[3]), "r"(b0), "r"(b1));
}
__device__ __forceinline__ uint32_t pack_bf2(float a, float b) {
    __nv_bfloat162 t = __floats2bfloat162_rn(a, b);
    uint32_t u;
    memcpy(&u, &t, 4);
    return u;
}
__device__ __forceinline__ uint32_t swz(int row, int kb) {
    int line  = row >> 1;
    int chunk = ((row & 1) << 2) | (kb >> 4);
    int phys  = chunk ^ (line & 7);
    return (uint32_t)(line * 128 + phys * 16 + (kb & 15));
}
__device__ __forceinline__ void cpasync16(uint32_t dst, const void* src, int sz) {
    asm volatile("cp.async.cg.shared.global [%0], [%1], 16, %2;"
                 :: "r"(dst), "l"(src), "r"(sz));
}

// ---------------- bf16 tensor-core GEMM (templated K, MODE) — R14 proven ----------------
// tile 256x64, BK=32, 4-stage cp.async ring, one __syncthreads per stage
#define ASTAGE 16384
#define BSTAGE 4096
#define STAGE  (ASTAGE + BSTAGE)
#define NSTG   4

template <int K, int MODE>
__global__ __launch_bounds__(256, 2) void gemm_tpl_kernel(
        const __nv_bfloat16* __restrict__ A,
        const __nv_bfloat16* __restrict__ W,
        const float* __restrict__ bias,
        const float* __restrict__ res,
        __nv_bfloat16* __restrict__ Cb,
        float* __restrict__ Cf,
        int M, int N) {
    extern __shared__ __align__(128) uint8_t smem[];
    const uint32_t sbase = (uint32_t)__cvta_generic_to_shared(smem);
    constexpr int NSTAGE = K / 32;
    static_assert(NSTAGE >= 4, "need at least 4 k-stages");

    const int tid = threadIdx.x, warp = tid >> 5, lane = tid & 31;
    const int wm = warp & 3, wn = warp >> 2;
    const int g = lane >> 2, tig = lane & 3;
    const int row0 = blockIdx.y * 256;
    const int col0 = blockIdx.x * 64;

    float acc[4][4][4] = {};

    const int quad = lane >> 3;
    const int rr = (quad & 1) * 8 + (lane & 7);
    const int kbq = (quad >> 1) * 16;
    const int ar = lane & 15, ac = (lane >> 4) * 16;
    const int lm = tid >> 2, lc = tid & 3;

    uint32_t aOf[4], bOf;
    const __nv_bfloat16* aP[4];
    int aSz[4];
    #pragma unroll
    for (int j = 0; j < 4; j++) {
        int m = lm + j * 64;
        aOf[j] = swz(m, lc * 16);
        aP[j]  = A + (size_t)(row0 + m) * K + lc * 8;
        aSz[j] = (row0 + m < M) ? 16 : 0;
    }
    bOf = swz(lm, lc * 16);
    const __nv_bfloat16* bP = W + (size_t)(col0 + lm) * K + lc * 8;

    auto load = [&](int stage) {
        uint32_t aB = sbase + (uint32_t)(stage & 3) * STAGE;
        #pragma unroll
        for (int j = 0; j < 4; j++) {
            cpasync16(aB + aOf[j], aP[j], aSz[j]);
            aP[j] += 32;
        }
        cpasync16(aB + ASTAGE + bOf, bP, 16);
        bP += 32;
        asm volatile("cp.async.commit_group;");
    };

    load(0); load(1); load(2);

    #pragma unroll
    for (int s = 0; s < NSTAGE; s++) {
        if (NSTAGE - 1 - s >= 2)      asm volatile("cp.async.wait_group 2;");
        else if (NSTAGE - 1 - s == 1) asm volatile("cp.async.wait_group 1;");
        else                          asm volatile("cp.async.wait_group 0;");
        __syncthreads();

        uint32_t aB = sbase + (uint32_t)(s & 3) * STAGE;
        uint32_t bB = aB + ASTAGE;
        #pragma unroll
        for (int ks = 0; ks < 2; ks++) {
            uint32_t afr[4][4], bfr[4][2];
            #pragma unroll
            for (int mi = 0; mi < 4; mi++)
                ldsm4(afr[mi], aB + swz(wm * 64 + mi * 16 + ar, ks * 32 + ac));
            #pragma unroll
            for (int np = 0; np < 2; np++) {
                uint32_t r4[4];
                ldsm4(r4, bB + swz(wn * 32 + np * 16 + rr, ks * 32 + kbq));
                bfr[np * 2 + 0][0] = r4[0]; bfr[np * 2 + 0][1] = r4[2];
                bfr[np * 2 + 1][0] = r4[1]; bfr[np * 2 + 1][1] = r4[3];
            }
            #pragma unroll
            for (int mi = 0; mi < 4; mi++)
                #pragma unroll
                for (int ni = 0; ni < 4; ni++)
                    mma_bf16(acc[mi][ni], afr[mi], bfr[ni][0], bfr[ni][1]);
        }

        if (s + 3 < NSTAGE) load(s + 3);
    }

    #pragma unroll
    for (int mi = 0; mi < 4; mi++) {
        #pragma unroll
        for (int hi = 0; hi < 2; hi++) {
            int r = row0 + wm * 64 + mi * 16 + g + hi * 8;
            if (r >= M) continue;
            #pragma unroll
            for (int ni = 0; ni < 4; ni++) {
                int c = col0 + wn * 32 + ni * 8 + 2 * tig;
                float v0 = acc[mi][ni][hi * 2 + 0] + bias[c];
                float v1 = acc[mi][ni][hi * 2 + 1] + bias[c + 1];
                if constexpr (MODE == 1) {
                    v0 = 0.5f * v0 * (1.0f + erff(v0 * 0.70710678118654752440f));
                    v1 = 0.5f * v1 * (1.0f + erff(v1 * 0.70710678118654752440f));
                }
                if constexpr (MODE == 2) {
                    const float2 rv = *(const float2*)(res + (size_t)r * N + c);
                    *(float2*)(Cf + (size_t)r * N + c) = make_float2(v0 + rv.x, v1 + rv.y);
                } else {
                    *(__nv_bfloat162*)(Cb + (size_t)r * N + c) = __floats2bfloat162_rn(v0, v1);
                }
            }
        }
    }
}

// ---------------- kernel 3: tensor-core windowed attention ----------------
__device__ __forceinline__ uint32_t swa(uint32_t base, int row, int chunk) {
    return base + row * 64 + ((chunk ^ ((row >> 1) & 3)) << 4);
}

__global__ __launch_bounds__(288, 2) void attn_kernel() {
    __shared__ __align__(128) __nv_bfloat16 sQ[144 * 32];
    __shared__ __align__(128) __nv_bfloat16 sK[144 * 32];
    __shared__ __align__(128) __nv_bfloat16 sV[144 * 32];

    const int blk = blockIdx.x;
    const int gwin = blk / HEADS, head = blk % HEADS;
    const int ilon = gwin / NW, iw = gwin % NW;
    const int tid = threadIdx.x;
    const size_t base = (size_t)gwin * NTOK;

    {
        const __nv_bfloat16* tb = g_qkv + base * 576 + head * 32;
        for (int i = tid; i < 576; i += 288) {
            int n = i >> 2, c = i & 3;
            int off = n * 32 + ((c ^ ((n >> 1) & 3)) << 3);
            const __nv_bfloat16* tp = tb + (size_t)n * 576 + c * 8;
            *(uint4*)(sQ + off) = *(const uint4*)(tp);
            *(uint4*)(sK + off) = *(const uint4*)(tp + 192);
            *(uint4*)(sV + off) = *(const uint4*)(tp + 384);
        }
    }
    __syncthreads();

    const uint32_t qB = (uint32_t)__cvta_generic_to_shared(sQ);
    const uint32_t kB = (uint32_t)__cvta_generic_to_shared(sK);
    const uint32_t vB = (uint32_t)__cvta_generic_to_shared(sV);

    const int warp = tid >> 5, lane = tid & 31;
    const int g = lane >> 2, tig = lane & 3;
    const int m0 = warp * 16;

    uint32_t aq[2][4];
    #pragma unroll
    for (int kq = 0; kq < 2; kq++)
        ldsm4(aq[kq], swa(qB, m0 + (lane & 15), kq * 2 + (lane >> 4)));

    const __nv_bfloat16* bm = g_bmask
        + ((size_t)((ilon == 14 ? 1 : 0) * 384 + iw * HEADS + head)) * (NTOK * NTOK);
    const int r0 = m0 + g, r1 = r0 + 8;

    float den0 = 0.f, den1 = 0.f;
    float o[4][4] = {};

    #pragma unroll
    for (int ph = 0; ph < 2; ph++) {
        const int ntS = ph ? 10 : 0, ntE = ph ? 18 : 10;
        const int kcS = ph ? 5 : 0,  kcE = ph ? 9 : 5;

        float acc[10][4];
        #pragma unroll
        for (int j = 0; j < 10; j++)
            #pragma unroll
            for (int q = 0; q < 4; q++) acc[j][q] = 0.f;

        for (int nt = ntS; nt < ntE; nt++) {
            uint32_t bk[4];
            ldsm4(bk, swa(kB, nt * 8 + (lane & 7), lane >> 3));
            mma_bf16(acc[nt - ntS], aq[0], bk[0], bk[1]);
            mma_bf16(acc[nt - ntS], aq[1], bk[2], bk[3]);
        }

        uint32_t paLo[10], paHi[10];
        for (int nt = ntS; nt < ntE; nt++) {
            int j = nt - ntS;
            int c0 = nt * 8 + 2 * tig;
            __nv_bfloat162 b0 = *(const __nv_bfloat162*)(bm + (size_t)r0 * 144 + c0);
            __nv_bfloat162 b1 = *(const __nv_bfloat162*)(bm + (size_t)r1 * 144 + c0);
            float p0 = __expf(fmaf(acc[j][0], QKSCALE, __bfloat162float(b0.x)));
            float p1 = __expf(fmaf(acc[j][1], QKSCALE, __bfloat162float(b0.y)));
            float p2 = __expf(fmaf(acc[j][2], QKSCALE, __bfloat162float(b1.x)));
            float p3 = __expf(fmaf(acc[j][3], QKSCALE, __bfloat162float(b1.y)));
            den0 += p0 + p1; den1 += p2 + p3;
            paLo[j] = pack_bf2(p0, p1);
            paHi[j] = pack_bf2(p2, p3);
        }

        for (int kc = kcS; kc < kcE; kc++) {
            int j2 = 2 * (kc - kcS);
            uint32_t Afr[4] = {paLo[j2], paHi[j2], paLo[j2 + 1], paHi[j2 + 1]};
            #pragma unroll
            for (int np = 0; np < 2; np++) {
                uint32_t bv[4];
                ldsm4t(bv, swa(vB, kc * 16 + ((lane >> 3) & 1) * 8 + (lane & 7),
                               np * 2 + (lane >> 4)));
                mma_bf16(o[np * 2 + 0], Afr, bv[0], bv[1]);
                mma_bf16(o[np * 2 + 1], Afr, bv[2], bv[3]);
            }
        }
    }

    den0 += __shfl_xor_sync(0xffffffffu, den0, 1);
    den0 += __shfl_xor_sync(0xffffffffu, den0, 2);
    den1 += __shfl_xor_sync(0xffffffffu, den1, 1);
    den1 += __shfl_xor_sync(0xffffffffu, den1, 2);
    float inv0 = 1.f / den0, inv1 = 1.f / den1;

    __nv_bfloat16* ob = g_att + base * DIM + head * HD;
    #pragma unroll
    for (int nt4 = 0; nt4 < 4; nt4++) {
        int col = nt4 * 8 + 2 * tig;
        *(__nv_bfloat162*)(ob + (size_t)r0 * DIM + col) =
            __floats2bfloat162_rn(o[nt4][0] * inv0, o[nt4][1] * inv0);
        *(__nv_bfloat162*)(ob + (size_t)r1 * DIM + col) =
            __floats2bfloat162_rn(o[nt4][2] * inv1, o[nt4][3] * inv1);
    }
}

// ---------------- kernel 5: scatter + residual + LN2 ----------------
__global__ void resid_ln2_kernel(const float* __restrict__ x,
                                 const float* __restrict__ w2,
                                 const float* __restrict__ b2) {
    int warp = threadIdx.x >> 5, lane = threadIdx.x & 31;
    int t = blockIdx.x * 8 + warp;
    int lon = t % 180;
    int lat = (t / 180) % 91;
    int pl  = t / (180 * 91);
    int pl_r  = (pl + 7) & 7;
    int lat_r = lat - 1; if (lat_r < 0) lat_r += 96;
    int lon_r = lon - 6; if (lon_r < 0) lon_r += 180;
    int ilon = lon_r / 12, ww = lon_r % 12;
    int ipl = pl_r >> 1,  z  = pl_r & 1;
    int ilat = lat_r / 6, hh = lat_r % 6;
    size_t wt = (size_t)(ilon * NW + ipl * 16 + ilat) * NTOK + z * 72 + hh * 12 + ww;

    const float* xs = x + (size_t)t * DIM;
    const __nv_bfloat16* ps = g_proj + wt * DIM;
    float v[6]; float s = 0.f, qq = 0.f;
    #pragma unroll
    for (int j = 0; j < 6; j++) {
        int c = lane + 32 * j;
        v[j] = xs[c] + __bfloat162float(ps[c]);
        s += v[j]; qq += v[j] * v[j];
    }
    #pragma unroll
    for (int o = 16; o > 0; o >>= 1) {
        s  += __shfl_xor_sync(0xffffffffu, s, o);
        qq += __shfl_xor_sync(0xffffffffu, qq, o);
    }
    float mean = s * (1.f / 192.f);
    float var  = qq * (1.f / 192.f) - mean * mean;
    float rs = rsqrtf(var + EPSLN);
    #pragma unroll
    for (int j = 0; j < 6; j++) {
        int c = lane + 32 * j;
        g_x1[(size_t)t * DIM + c] = v[j];
        g_h2[(size_t)t * DIM + c] = __float2bfloat16((v[j] - mean) * rs * w2[c] + b2[c]);
    }
}

// ---------------- launcher ----------------
extern "C" void kernel_launch(void* const* d_in, const int* in_sizes, int n_in,
                              void* d_out, int out_size) {
    const float* x     = (const float*)d_in[0];
    const float* n1w   = (const float*)d_in[1];
    const float* n1b   = (const float*)d_in[2];
    const float* qkvw  = (const float*)d_in[3];
    const float* qkvb  = (const float*)d_in[4];
    const float* btab  = (const float*)d_in[5];
    const float* projw = (const float*)d_in[6];
    const float* projb = (const float*)d_in[7];
    const float* n2w   = (const float*)d_in[8];
    const float* n2b   = (const float*)d_in[9];
    const float* fc1w  = (const float*)d_in[10];
    const float* fc1b  = (const float*)d_in[11];
    const float* fc2w  = (const float*)d_in[12];
    const float* fc2b  = (const float*)d_in[13];
    float* out = (float*)d_out;

    __nv_bfloat16 *p_h, *p_qkv, *p_att, *p_proj, *p_h2, *p_fc1;
    __nv_bfloat16 *p_wq, *p_wp, *p_w1, *p_w2;
    float *p_x1;
    cudaGetSymbolAddress((void**)&p_h,    g_h);
    cudaGetSymbolAddress((void**)&p_qkv,  g_qkv);
    cudaGetSymbolAddress((void**)&p_att,  g_att);
    cudaGetSymbolAddress((void**)&p_proj, g_proj);
    cudaGetSymbolAddress((void**)&p_x1,   g_x1);
    cudaGetSymbolAddress((void**)&p_h2,   g_h2);
    cudaGetSymbolAddress((void**)&p_fc1,  g_fc1);
    cudaGetSymbolAddress((void**)&p_wq,   g_wq);
    cudaGetSymbolAddress((void**)&p_wp,   g_wp);
    cudaGetSymbolAddress((void**)&p_w1,   g_w1);
    cudaGetSymbolAddress((void**)&p_w2,   g_w2);

    static int s_init = 0;
    static cudaStream_t sW, sB;
    static cudaEvent_t evFork, evW, evB;
    if (!s_init) {
        cudaFuncSetAttribute(gemm_tpl_kernel<192, 0>,
                             cudaFuncAttributeMaxDynamicSharedMemorySize, NSTG * STAGE);
        cudaFuncSetAttribute(gemm_tpl_kernel<192, 1>,
                             cudaFuncAttributeMaxDynamicSharedMemorySize, NSTG * STAGE);
        cudaFuncSetAttribute(gemm_tpl_kernel<768, 2>,
                             cudaFuncAttributeMaxDynamicSharedMemorySize, NSTG * STAGE);
        cudaStreamCreateWithFlags(&sW, cudaStreamNonBlocking);
        cudaStreamCreateWithFlags(&sB, cudaStreamNonBlocking);
        cudaEventCreateWithFlags(&evFork, cudaEventDisableTiming);
        cudaEventCreateWithFlags(&evW,    cudaEventDisableTiming);
        cudaEventCreateWithFlags(&evB,    cudaEventDisableTiming);
        s_init = 1;
    }

    // fork side streams for prep (validated capture-safe in R15)
    cudaEventRecord(evFork, 0);
    cudaStreamWaitEvent(sW, evFork, 0);
    cudaStreamWaitEvent(sB, evFork, 0);

    cvtall_kernel<<<(442368 + 255) / 256, 256, 0, sW>>>(qkvw, projw, fc1w, fc2w);
    cudaEventRecord(evW, sW);

    bmask_kernel<<<768, 256, 0, sB>>>(btab);
    cudaEventRecord(evB, sB);

    // main: LN1 + window partition (overlaps both prep streams)
    ln1_window_kernel<<<WTOK / 8, 256>>>(x, n1w, n1b);

    // 2. QKV gemm (needs weights)
    cudaStreamWaitEvent(0, evW, 0);
    gemm_tpl_kernel<192, 0><<<dim3(9, WTOK / 256), 256, NSTG * STAGE>>>(
        p_h, p_wq, qkvb, nullptr, p_qkv, nullptr, WTOK, 576);

    // 3. attention (needs bmask)
    cudaStreamWaitEvent(0, evB, 0);
    attn_kernel<<<NLON * NW * HEADS, 288>>>();

    // 4. proj gemm
    gemm_tpl_kernel<192, 0><<<dim3(3, WTOK / 256), 256, NSTG * STAGE>>>(
        p_att, p_wp, projb, nullptr, p_proj, nullptr, WTOK, 192);

    // 5. scatter + residual + LN2
    resid_ln2_kernel<<<LTOK / 8, 256>>>(x, n2w, n2b);

    // 6. fc1 gemm + gelu
    gemm_tpl_kernel<192, 1><<<dim3(12, (LTOK + 255) / 256), 256, NSTG * STAGE>>>(
        p_h2, p_w1, fc1b, nullptr, p_fc1, nullptr, LTOK, 768);

    // 7. fc2 gemm + residual -> out
    gemm_tpl_kernel<768, 2><<<dim3(3, (LTOK + 255) / 256), 256, NSTG * STAGE>>>(
        p_fc1, p_w2, fc2b, p_x1, nullptr, out, LTOK, 192);
}